// round 8
// baseline (speedup 1.0000x reference)
#include <cuda_runtime.h>
#include <cuda_bf16.h>
#include <cstdint>

// ---------------- problem constants ----------------
#define T_CO 16
#define BATCH 16
#define NH 28
#define NW 28
#define CCH 64
#define KCH 64
#define ROW_FLOATS (NW * CCH)                  // 1792
#define TRANS_T_STRIDE (BATCH * NH * NW * CCH) // 802816
#define TRANS_B_STRIDE (NH * NW * CCH)         // 50176

#define NTHREADS 1024

// per-t smem slot (bytes): A frags (hi 4096 + lo 4096) during GEMM,
// then reused as mix[t] (28 rows x 288B = 8064B)
#define SLOT 8192
#define SMEM_BYTES (T_CO * SLOT)               // 131072
#define MIX_ROW 288                            // 72 floats per mix row

// ---------------- weight fragments (prepacked) ----------------
// layout [s][t][phys 8][nt 8][lane 32][2] b32 ; phys 0-3 = Bhi ktiles, 4-7 = Blo
__device__ uint32_t g_wfrag[2 * T_CO * 8 * 8 * 64];   // 512 KB

__device__ __forceinline__ uint32_t pack_bf16x2(float lo_elem, float hi_elem) {
    // returns {upper16 = bf16(hi_elem), lower16 = bf16(lo_elem)}
    uint32_t r;
    asm("cvt.rn.bf16x2.f32 %0, %1, %2;" : "=r"(r) : "f"(hi_elem), "f"(lo_elem));
    return r;
}

__global__ void prep_weights(const float* __restrict__ w1, const float* __restrict__ w2) {
    int idx = blockIdx.x * 256 + threadIdx.x;      // 131072 total
    int r    = idx & 1;
    int lane = (idx >> 1) & 31;
    int nt   = (idx >> 6) & 7;
    int phys = (idx >> 9) & 7;
    int t    = (idx >> 12) & 15;
    int s    = idx >> 16;
    const float* w = s ? w2 : w1;
    int kchan = nt * 8 + (lane >> 2);
    int c     = (phys & 3) * 16 + (lane & 3) * 2 + r * 8;
    float v0 = w[(t * 64 + c) * 64 + kchan];
    float v1 = w[(t * 64 + c + 1) * 64 + kchan];
    if (phys >= 4) {   // lo residual tiles
        v0 = v0 - __bfloat162float(__float2bfloat16_rn(v0));
        v1 = v1 - __bfloat162float(__float2bfloat16_rn(v1));
    }
    g_wfrag[idx] = pack_bf16x2(v0, v1);
}

// ---------------- main kernel ----------------
__device__ __forceinline__ float2 f2add(float2 a, float2 b) { return make_float2(a.x + b.x, a.y + b.y); }
__device__ __forceinline__ float2 f2sub(float2 a, float2 b) { return make_float2(a.x - b.x, a.y - b.y); }

#define MMA16816(d, a, b0, b1)                                               \
    asm("mma.sync.aligned.m16n8k16.row.col.f32.bf16.bf16.f32 "               \
        "{%0,%1,%2,%3},{%4,%5,%6,%7},{%8,%9},{%0,%1,%2,%3};"                 \
        : "+f"((d)[0]), "+f"((d)[1]), "+f"((d)[2]), "+f"((d)[3])             \
        : "r"((a).x), "r"((a).y), "r"((a).z), "r"((a).w), "r"(b0), "r"(b1))

__global__ void __launch_bounds__(NTHREADS, 1)
iwht2_mma_kernel(const float* __restrict__ tr1, const float* __restrict__ tr2,
                 const float* __restrict__ b1,  const float* __restrict__ b2,
                 float* __restrict__ out, size_t out_stream_stride)
{
    extern __shared__ char smc[];

    const int bi  = blockIdx.x;
    const int s   = bi / (BATCH * NH);
    const int rem = bi - s * (BATCH * NH);
    const int b   = rem / NH;
    const int h   = rem - b * NH;

    const float* tr = s ? tr2 : tr1;
    const float* bs = s ? b2  : b1;
    float* outp = out + (size_t)s * out_stream_stride;

    const int tid   = threadIdx.x;
    const int t     = tid >> 6;           // coefficient: one warp PAIR per t
    const int khalf = (tid >> 5) & 1;     // n-half within the pair
    const int lane  = tid & 31;
    const int lane64 = tid & 63;
    const int g    = lane >> 2;           // group id (rows)
    const int tg   = lane & 3;            // thread-in-group (cols)
    const int barid = 1 + (t >> 1);       // quad barrier ids 1..8 (0 = __syncthreads)
    char* tslot = smc + t * SLOT;

    // ---- stage A (shared by the pair): trans tile -> bf16 hi/lo fragments ----
    {
        const float4* gsrc = (const float4*)(tr + (size_t)b * TRANS_B_STRIDE
                                                + (size_t)h * ROW_FLOATS
                                                + (size_t)t * TRANS_T_STRIDE);
        #pragma unroll
        for (int i = 0; i < 7; i++) {
            int idx = i * 64 + lane64;         // 0..447 float4s
            int row = idx >> 4;                // 0..27
            int c4  = idx & 15;
            float4 v = __ldg(gsrc + idx);

            int mt  = row >> 4;
            int rp  = row & 15;
            int gg  = rp & 7;
            int rb  = rp >> 3;                 // 0 -> a0/a2, 1 -> a1/a3
            int kt  = c4 >> 2;
            int cpp = (c4 & 3) * 4;            // within-tile col base {0,4,8,12}
            int areg = rb + ((cpp >= 8) ? 2 : 0);
            int L0   = gg * 4 + ((cpp & 7) >> 1);

            uint32_t h0 = pack_bf16x2(v.x, v.y);
            uint32_t h1 = pack_bf16x2(v.z, v.w);
            float lx = v.x - __uint_as_float(h0 << 16);
            float ly = v.y - __uint_as_float(h0 & 0xffff0000u);
            float lz = v.z - __uint_as_float(h1 << 16);
            float lw = v.w - __uint_as_float(h1 & 0xffff0000u);
            uint32_t l0 = pack_bf16x2(lx, ly);
            uint32_t l1 = pack_bf16x2(lz, lw);

            uint32_t off0 = mt * 2048 + kt * 512 + (((L0)     ^ (kt << 1)) << 4) + areg * 4;
            uint32_t off1 = mt * 2048 + kt * 512 + (((L0 + 1) ^ (kt << 1)) << 4) + areg * 4;
            *(uint32_t*)(tslot + off0)        = h0;
            *(uint32_t*)(tslot + off1)        = h1;
            *(uint32_t*)(tslot + 4096 + off0) = l0;
            *(uint32_t*)(tslot + 4096 + off1) = l1;
        }
    }
    // quad barrier (4 warps = 2 pairs): A tiles staged before fragments are read
    asm volatile("bar.sync %0, 128;" :: "r"(barid) : "memory");

    // ---- GEMM: D(28x32slice) = A''(28x192) x B''(192x32slice), 3-term bf16 split ----
    float acc[2][4][4];
    #pragma unroll
    for (int mt = 0; mt < 2; mt++)
        #pragma unroll
        for (int nt = 0; nt < 4; nt++)
            #pragma unroll
            for (int j = 0; j < 4; j++) acc[mt][nt][j] = 0.0f;

    const uint32_t* gw = g_wfrag + (size_t)(s * T_CO + t) * (8 * 512) + khalf * 4 * 64;

    #pragma unroll
    for (int ki = 0; ki < 12; ki++) {
        const int hl   = (ki >= 8) ? 1 : 0;          // ki 0-7: Ahi, 8-11: Alo
        const int ktp  = ki & 3;
        const int phys = (ki < 8) ? ki : (ki - 8);   // B: hi(0-3), lo(4-7), hi(0-3)

        uint4 A0 = *(const uint4*)(tslot + hl * 4096 + 0    + ktp * 512
                                   + ((lane ^ (ktp << 1)) << 4));
        uint4 A1 = *(const uint4*)(tslot + hl * 4096 + 2048 + ktp * 512
                                   + ((lane ^ (ktp << 1)) << 4));
        #pragma unroll
        for (int nt = 0; nt < 4; nt++) {
            uint2 bv = *(const uint2*)(gw + (phys * 8 + nt) * 64 + lane * 2);
            MMA16816(acc[0][nt], A0, bv.x, bv.y);
            MMA16816(acc[1][nt], A1, bv.x, bv.y);
        }
    }

    // quad barrier: all 4 warps done reading A before D overwrites the slots
    asm volatile("bar.sync %0, 128;" :: "r"(barid) : "memory");

    // ---- write D into mix slot (reuses the pair's A region) ----
    #pragma unroll
    for (int mt = 0; mt < 2; mt++) {
        #pragma unroll
        for (int nt = 0; nt < 4; nt++) {
            int row0 = mt * 16 + g;
            int kp   = (khalf * 4 + nt) * 4 + tg;
            *(float2*)(tslot + row0 * MIX_ROW + kp * 8) =
                make_float2(acc[mt][nt][0], acc[mt][nt][1]);
            int row1 = row0 + 8;
            if (row1 < 28)
                *(float2*)(tslot + row1 * MIX_ROW + kp * 8) =
                    make_float2(acc[mt][nt][2], acc[mt][nt][3]);
        }
    }
    __syncthreads();

    // ---- combine: inverse 2D 4-pt WHT over t = 4u+v, scale 1/16, + bias ----
    if (tid < 896) {                       // w(28) x kpair(32)
        const int wrow = tid >> 5;
        const int kp   = tid & 31;

        float2 m[16];
        #pragma unroll
        for (int tt = 0; tt < 16; tt++)
            m[tt] = *(const float2*)(smc + tt * SLOT + wrow * MIX_ROW + kp * 8);

        #pragma unroll
        for (int u = 0; u < 4; u++) {
            float2 m0 = m[4*u], m1 = m[4*u+1], m2 = m[4*u+2], m3 = m[4*u+3];
            float2 s0 = f2add(m0, m1), d0 = f2sub(m0, m1);
            float2 s1 = f2add(m2, m3), d1 = f2sub(m2, m3);
            m[4*u + 0] = f2add(s0, s1);
            m[4*u + 1] = f2add(d0, d1);
            m[4*u + 2] = f2sub(s0, s1);
            m[4*u + 3] = f2sub(d0, d1);
        }

        const float2 bv = ((const float2*)bs)[kp];
        float* op = outp + (size_t)b * (112 * 112 * 64)
                         + (size_t)h * (4 * 112 * 64)
                         + (size_t)wrow * (4 * 64)
                         + 2 * kp;

        #pragma unroll
        for (int j = 0; j < 4; j++) {
            float2 r0 = m[j], r1 = m[4 + j], r2 = m[8 + j], r3 = m[12 + j];
            float2 s0 = f2add(r0, r1), d0 = f2sub(r0, r1);
            float2 s1 = f2add(r2, r3), d1 = f2sub(r2, r3);
            float2 o0 = f2add(s0, s1);
            float2 o1 = f2add(d0, d1);
            float2 o2 = f2sub(s0, s1);
            float2 o3 = f2sub(d0, d1);
            float2 v0 = make_float2(fmaf(o0.x, 0.0625f, bv.x), fmaf(o0.y, 0.0625f, bv.y));
            float2 v1 = make_float2(fmaf(o1.x, 0.0625f, bv.x), fmaf(o1.y, 0.0625f, bv.y));
            float2 v2 = make_float2(fmaf(o2.x, 0.0625f, bv.x), fmaf(o2.y, 0.0625f, bv.y));
            float2 v3 = make_float2(fmaf(o3.x, 0.0625f, bv.x), fmaf(o3.y, 0.0625f, bv.y));
            *reinterpret_cast<float2*>(op + 0 * 7168 + j * 64) = v0;
            *reinterpret_cast<float2*>(op + 1 * 7168 + j * 64) = v1;
            *reinterpret_cast<float2*>(op + 2 * 7168 + j * 64) = v2;
            *reinterpret_cast<float2*>(op + 3 * 7168 + j * 64) = v3;
        }
    }
}

extern "C" void kernel_launch(void* const* d_in, const int* in_sizes, int n_in,
                              void* d_out, int out_size) {
    (void)in_sizes; (void)n_in;
    const float* tr1 = (const float*)d_in[0];
    const float* tr2 = (const float*)d_in[1];
    const float* w1  = (const float*)d_in[2];
    const float* w2  = (const float*)d_in[3];
    const float* b1  = (const float*)d_in[4];
    const float* b2  = (const float*)d_in[5];
    float* out = (float*)d_out;

    prep_weights<<<512, 256>>>(w1, w2);

    cudaFuncSetAttribute(iwht2_mma_kernel,
                         cudaFuncAttributeMaxDynamicSharedMemorySize, SMEM_BYTES);
    size_t stream_stride = (size_t)out_size / 2;   // out1 then out2
    iwht2_mma_kernel<<<2 * BATCH * NH, NTHREADS, SMEM_BYTES>>>(
        tr1, tr2, b1, b2, out, stream_stride);
}

// round 9
// speedup vs baseline: 1.3080x; 1.3080x over previous
#include <cuda_runtime.h>
#include <cuda_bf16.h>
#include <cstdint>

// ---------------- problem constants ----------------
#define T_CO 16
#define BATCH 16
#define NH 28
#define NW 28
#define CCH 64
#define KCH 64
#define ROW_FLOATS (NW * CCH)                  // 1792
#define TRANS_T_STRIDE (BATCH * NH * NW * CCH) // 802816
#define TRANS_B_STRIDE (NH * NW * CCH)         // 50176

#define NTHREADS 1024

// per-t smem slot (bytes): A frags (hi 4096 + lo 4096) during GEMM,
// then reused as mix[t] (28 rows x 288B = 8064B)
#define SLOT 8192
#define SMEM_BYTES (T_CO * SLOT)               // 131072
#define MIX_ROW 288                            // 72 floats per mix row

// ---------------- weight fragments (prepacked) ----------------
// layout [s][t][phys 8][nt 8][lane 32][2] b32 ; phys 0-3 = Bhi ktiles, 4-7 = Blo
__device__ uint32_t g_wfrag[2 * T_CO * 8 * 8 * 64];   // 512 KB

__device__ __forceinline__ uint32_t pack_bf16x2(float lo_elem, float hi_elem) {
    // returns {upper16 = bf16(hi_elem), lower16 = bf16(lo_elem)}
    uint32_t r;
    asm("cvt.rn.bf16x2.f32 %0, %1, %2;" : "=r"(r) : "f"(hi_elem), "f"(lo_elem));
    return r;
}

__global__ void prep_weights(const float* __restrict__ w1, const float* __restrict__ w2) {
    int idx = blockIdx.x * 256 + threadIdx.x;      // 131072 total
    int r    = idx & 1;
    int lane = (idx >> 1) & 31;
    int nt   = (idx >> 6) & 7;
    int phys = (idx >> 9) & 7;
    int t    = (idx >> 12) & 15;
    int s    = idx >> 16;
    const float* w = s ? w2 : w1;
    int kchan = nt * 8 + (lane >> 2);
    int c     = (phys & 3) * 16 + (lane & 3) * 2 + r * 8;
    float v0 = w[(t * 64 + c) * 64 + kchan];
    float v1 = w[(t * 64 + c + 1) * 64 + kchan];
    if (phys >= 4) {   // lo residual tiles
        v0 = v0 - __bfloat162float(__float2bfloat16_rn(v0));
        v1 = v1 - __bfloat162float(__float2bfloat16_rn(v1));
    }
    g_wfrag[idx] = pack_bf16x2(v0, v1);
}

// ---------------- main kernel ----------------
__device__ __forceinline__ float2 f2add(float2 a, float2 b) { return make_float2(a.x + b.x, a.y + b.y); }
__device__ __forceinline__ float2 f2sub(float2 a, float2 b) { return make_float2(a.x - b.x, a.y - b.y); }

#define MMA16816(d, a, b0, b1)                                               \
    asm("mma.sync.aligned.m16n8k16.row.col.f32.bf16.bf16.f32 "               \
        "{%0,%1,%2,%3},{%4,%5,%6,%7},{%8,%9},{%0,%1,%2,%3};"                 \
        : "+f"((d)[0]), "+f"((d)[1]), "+f"((d)[2]), "+f"((d)[3])             \
        : "r"((a).x), "r"((a).y), "r"((a).z), "r"((a).w), "r"(b0), "r"(b1))

__global__ void __launch_bounds__(NTHREADS, 1)
iwht2_mma_kernel(const float* __restrict__ tr1, const float* __restrict__ tr2,
                 const float* __restrict__ b1,  const float* __restrict__ b2,
                 float* __restrict__ out, size_t out_stream_stride)
{
    extern __shared__ char smc[];

    const int bi  = blockIdx.x;
    const int s   = bi / (BATCH * NH);
    const int rem = bi - s * (BATCH * NH);
    const int b   = rem / NH;
    const int h   = rem - b * NH;

    const float* tr = s ? tr2 : tr1;
    const float* bs = s ? b2  : b1;
    float* outp = out + (size_t)s * out_stream_stride;

    const int tid   = threadIdx.x;
    const int t     = tid >> 6;           // coefficient: one warp PAIR per t
    const int khalf = (tid >> 5) & 1;     // n-half within the pair
    const int lane  = tid & 31;
    const int lane64 = tid & 63;
    const int g    = lane >> 2;           // group id (rows)
    const int tg   = lane & 3;            // thread-in-group (cols)
    const int barid = 1 + (t >> 1);       // quad barrier ids 1..8 (0 = __syncthreads)
    char* tslot = smc + t * SLOT;

    // ---- stage A (shared by the pair): trans tile -> bf16 hi/lo fragments ----
    {
        const float4* gsrc = (const float4*)(tr + (size_t)b * TRANS_B_STRIDE
                                                + (size_t)h * ROW_FLOATS
                                                + (size_t)t * TRANS_T_STRIDE);
        #pragma unroll
        for (int i = 0; i < 7; i++) {
            int idx = i * 64 + lane64;         // 0..447 float4s
            int row = idx >> 4;                // 0..27
            int c4  = idx & 15;
            float4 v = __ldg(gsrc + idx);

            int mt  = row >> 4;
            int rp  = row & 15;
            int gg  = rp & 7;
            int rb  = rp >> 3;                 // 0 -> a0/a2, 1 -> a1/a3
            int kt  = c4 >> 2;
            int cpp = (c4 & 3) * 4;            // within-tile col base {0,4,8,12}
            int areg = rb + ((cpp >= 8) ? 2 : 0);
            int L0   = gg * 4 + ((cpp & 7) >> 1);

            uint32_t h0 = pack_bf16x2(v.x, v.y);
            uint32_t h1 = pack_bf16x2(v.z, v.w);
            float lx = v.x - __uint_as_float(h0 << 16);
            float ly = v.y - __uint_as_float(h0 & 0xffff0000u);
            float lz = v.z - __uint_as_float(h1 << 16);
            float lw = v.w - __uint_as_float(h1 & 0xffff0000u);
            uint32_t l0 = pack_bf16x2(lx, ly);
            uint32_t l1 = pack_bf16x2(lz, lw);

            uint32_t off0 = mt * 2048 + kt * 512 + (((L0)     ^ (kt << 1)) << 4) + areg * 4;
            uint32_t off1 = mt * 2048 + kt * 512 + (((L0 + 1) ^ (kt << 1)) << 4) + areg * 4;
            *(uint32_t*)(tslot + off0)        = h0;
            *(uint32_t*)(tslot + off1)        = h1;
            *(uint32_t*)(tslot + 4096 + off0) = l0;
            *(uint32_t*)(tslot + 4096 + off1) = l1;
        }
    }
    // quad barrier (4 warps = 2 pairs): A tiles staged before fragments are read
    asm volatile("bar.sync %0, 128;" :: "r"(barid) : "memory");

    // ---- GEMM: D(28x32slice) = A''(28x192) x B''(192x32slice), 3-term bf16 split ----
    float acc[2][4][4];
    #pragma unroll
    for (int mt = 0; mt < 2; mt++)
        #pragma unroll
        for (int nt = 0; nt < 4; nt++)
            #pragma unroll
            for (int j = 0; j < 4; j++) acc[mt][nt][j] = 0.0f;

    // uint2-granular fragment pointer for this (s,t,khalf,lane)
    const uint2* gwl = (const uint2*)(g_wfrag + (size_t)(s * T_CO + t) * (8 * 512))
                       + (size_t)khalf * 4 * 32 + lane;

    #pragma unroll 1
    for (int ki = 0; ki < 12; ki++) {
        const int hl   = (ki >= 8) ? 1 : 0;          // ki 0-7: Ahi, 8-11: Alo
        const int ktp  = ki & 3;
        const int phys = (ki < 8) ? ki : (ki - 8);   // B: hi(0-3), lo(4-7), hi(0-3)

        // 4 independent B-fragment loads first (MLP within the iteration)
        uint2 bv0 = gwl[(phys * 8 + 0) * 32];
        uint2 bv1 = gwl[(phys * 8 + 1) * 32];
        uint2 bv2 = gwl[(phys * 8 + 2) * 32];
        uint2 bv3 = gwl[(phys * 8 + 3) * 32];

        const char* abase = tslot + hl * 4096 + ktp * 512 + ((lane ^ (ktp << 1)) << 4);
        uint4 A0 = *(const uint4*)(abase);
        uint4 A1 = *(const uint4*)(abase + 2048);

        MMA16816(acc[0][0], A0, bv0.x, bv0.y);
        MMA16816(acc[1][0], A1, bv0.x, bv0.y);
        MMA16816(acc[0][1], A0, bv1.x, bv1.y);
        MMA16816(acc[1][1], A1, bv1.x, bv1.y);
        MMA16816(acc[0][2], A0, bv2.x, bv2.y);
        MMA16816(acc[1][2], A1, bv2.x, bv2.y);
        MMA16816(acc[0][3], A0, bv3.x, bv3.y);
        MMA16816(acc[1][3], A1, bv3.x, bv3.y);
    }

    // quad barrier: all 4 warps done reading A before D overwrites the slots
    asm volatile("bar.sync %0, 128;" :: "r"(barid) : "memory");

    // ---- write D into mix slot (reuses the pair's A region) ----
    #pragma unroll
    for (int mt = 0; mt < 2; mt++) {
        #pragma unroll
        for (int nt = 0; nt < 4; nt++) {
            int row0 = mt * 16 + g;
            int kp   = (khalf * 4 + nt) * 4 + tg;
            *(float2*)(tslot + row0 * MIX_ROW + kp * 8) =
                make_float2(acc[mt][nt][0], acc[mt][nt][1]);
            int row1 = row0 + 8;
            if (row1 < 28)
                *(float2*)(tslot + row1 * MIX_ROW + kp * 8) =
                    make_float2(acc[mt][nt][2], acc[mt][nt][3]);
        }
    }
    __syncthreads();

    // ---- combine: inverse 2D 4-pt WHT over t = 4u+v, scale 1/16, + bias ----
    if (tid < 896) {                       // w(28) x kpair(32)
        const int wrow = tid >> 5;
        const int kp   = tid & 31;

        float2 m[16];
        #pragma unroll
        for (int tt = 0; tt < 16; tt++)
            m[tt] = *(const float2*)(smc + tt * SLOT + wrow * MIX_ROW + kp * 8);

        #pragma unroll
        for (int u = 0; u < 4; u++) {
            float2 m0 = m[4*u], m1 = m[4*u+1], m2 = m[4*u+2], m3 = m[4*u+3];
            float2 s0 = f2add(m0, m1), d0 = f2sub(m0, m1);
            float2 s1 = f2add(m2, m3), d1 = f2sub(m2, m3);
            m[4*u + 0] = f2add(s0, s1);
            m[4*u + 1] = f2add(d0, d1);
            m[4*u + 2] = f2sub(s0, s1);
            m[4*u + 3] = f2sub(d0, d1);
        }

        const float2 bv = ((const float2*)bs)[kp];
        float* op = outp + (size_t)b * (112 * 112 * 64)
                         + (size_t)h * (4 * 112 * 64)
                         + (size_t)wrow * (4 * 64)
                         + 2 * kp;

        #pragma unroll
        for (int j = 0; j < 4; j++) {
            float2 r0 = m[j], r1 = m[4 + j], r2 = m[8 + j], r3 = m[12 + j];
            float2 s0 = f2add(r0, r1), d0 = f2sub(r0, r1);
            float2 s1 = f2add(r2, r3), d1 = f2sub(r2, r3);
            float2 o0 = f2add(s0, s1);
            float2 o1 = f2add(d0, d1);
            float2 o2 = f2sub(s0, s1);
            float2 o3 = f2sub(d0, d1);
            float2 v0 = make_float2(fmaf(o0.x, 0.0625f, bv.x), fmaf(o0.y, 0.0625f, bv.y));
            float2 v1 = make_float2(fmaf(o1.x, 0.0625f, bv.x), fmaf(o1.y, 0.0625f, bv.y));
            float2 v2 = make_float2(fmaf(o2.x, 0.0625f, bv.x), fmaf(o2.y, 0.0625f, bv.y));
            float2 v3 = make_float2(fmaf(o3.x, 0.0625f, bv.x), fmaf(o3.y, 0.0625f, bv.y));
            *reinterpret_cast<float2*>(op + 0 * 7168 + j * 64) = v0;
            *reinterpret_cast<float2*>(op + 1 * 7168 + j * 64) = v1;
            *reinterpret_cast<float2*>(op + 2 * 7168 + j * 64) = v2;
            *reinterpret_cast<float2*>(op + 3 * 7168 + j * 64) = v3;
        }
    }
}

extern "C" void kernel_launch(void* const* d_in, const int* in_sizes, int n_in,
                              void* d_out, int out_size) {
    (void)in_sizes; (void)n_in;
    const float* tr1 = (const float*)d_in[0];
    const float* tr2 = (const float*)d_in[1];
    const float* w1  = (const float*)d_in[2];
    const float* w2  = (const float*)d_in[3];
    const float* b1  = (const float*)d_in[4];
    const float* b2  = (const float*)d_in[5];
    float* out = (float*)d_out;

    prep_weights<<<512, 256>>>(w1, w2);

    cudaFuncSetAttribute(iwht2_mma_kernel,
                         cudaFuncAttributeMaxDynamicSharedMemorySize, SMEM_BYTES);
    size_t stream_stride = (size_t)out_size / 2;   // out1 then out2
    iwht2_mma_kernel<<<2 * BATCH * NH, NTHREADS, SMEM_BYTES>>>(
        tr1, tr2, b1, b2, out, stream_stride);
}

// round 10
// speedup vs baseline: 1.6864x; 1.2893x over previous
#include <cuda_runtime.h>
#include <cuda_fp16.h>
#include <cstdint>

// ---------------- problem constants ----------------
#define T_CO 16
#define BATCH 16
#define NH 28
#define NW 28
#define CCH 64
#define KCH 64
#define ROW_FLOATS (NW * CCH)                  // 1792
#define TRANS_T_STRIDE (BATCH * NH * NW * CCH) // 802816
#define TRANS_B_STRIDE (NH * NW * CCH)         // 50176

#define NTHREADS 1024

// per-t smem slot (bytes): A frags (fp16 hi, 4096B) during GEMM,
// then reused as mix[t] (28 rows x 288B = 8064B)
#define SLOT 8192
#define SMEM_BYTES (T_CO * SLOT)               // 131072
#define MIX_ROW 288                            // 72 floats per mix row

// ---------------- weight fragments (prepacked fp16) ----------------
// layout [s][t][phys 8][nt 8][lane 32][2] b32 ; phys 0-3 = Bhi ktiles, 4-7 = Blo
__device__ uint32_t g_wfrag[2 * T_CO * 8 * 8 * 64];   // 512 KB

__device__ __forceinline__ uint32_t pack_f16x2(float lo_elem, float hi_elem) {
    // returns {upper16 = f16(hi_elem), lower16 = f16(lo_elem)}
    uint32_t r;
    asm("cvt.rn.f16x2.f32 %0, %1, %2;" : "=r"(r) : "f"(hi_elem), "f"(lo_elem));
    return r;
}

__global__ void prep_weights(const float* __restrict__ w1, const float* __restrict__ w2) {
    int idx = blockIdx.x * 256 + threadIdx.x;      // 131072 total
    int r    = idx & 1;
    int lane = (idx >> 1) & 31;
    int nt   = (idx >> 6) & 7;
    int phys = (idx >> 9) & 7;
    int t    = (idx >> 12) & 15;
    int s    = idx >> 16;
    const float* w = s ? w2 : w1;
    int kchan = nt * 8 + (lane >> 2);
    int c     = (phys & 3) * 16 + (lane & 3) * 2 + r * 8;
    float v0 = w[(t * 64 + c) * 64 + kchan];
    float v1 = w[(t * 64 + c + 1) * 64 + kchan];
    if (phys >= 4) {   // lo residual tiles
        v0 = v0 - __half2float(__float2half_rn(v0));
        v1 = v1 - __half2float(__float2half_rn(v1));
    }
    g_wfrag[idx] = pack_f16x2(v0, v1);
}

// ---------------- main kernel ----------------
__device__ __forceinline__ float2 f2add(float2 a, float2 b) { return make_float2(a.x + b.x, a.y + b.y); }
__device__ __forceinline__ float2 f2sub(float2 a, float2 b) { return make_float2(a.x - b.x, a.y - b.y); }

#define MMA16816(d, a, b0, b1)                                               \
    asm("mma.sync.aligned.m16n8k16.row.col.f32.f16.f16.f32 "                 \
        "{%0,%1,%2,%3},{%4,%5,%6,%7},{%8,%9},{%0,%1,%2,%3};"                 \
        : "+f"((d)[0]), "+f"((d)[1]), "+f"((d)[2]), "+f"((d)[3])             \
        : "r"((a).x), "r"((a).y), "r"((a).z), "r"((a).w), "r"(b0), "r"(b1))

__global__ void __launch_bounds__(NTHREADS, 1)
iwht2_mma_kernel(const float* __restrict__ tr1, const float* __restrict__ tr2,
                 const float* __restrict__ b1,  const float* __restrict__ b2,
                 float* __restrict__ out, size_t out_stream_stride)
{
    extern __shared__ char smc[];

    const int bi  = blockIdx.x;
    const int s   = bi / (BATCH * NH);
    const int rem = bi - s * (BATCH * NH);
    const int b   = rem / NH;
    const int h   = rem - b * NH;

    const float* tr = s ? tr2 : tr1;
    const float* bs = s ? b2  : b1;
    float* outp = out + (size_t)s * out_stream_stride;

    const int tid   = threadIdx.x;
    const int t     = tid >> 6;           // coefficient: one warp PAIR per t
    const int khalf = (tid >> 5) & 1;     // n-half within the pair
    const int lane  = tid & 31;
    const int lane64 = tid & 63;
    const int g    = lane >> 2;           // group id (rows)
    const int tg   = lane & 3;            // thread-in-group (cols)
    const int barid = 1 + (t >> 1);       // quad barrier ids 1..8 (0 = __syncthreads)
    char* tslot = smc + t * SLOT;

    // ---- stage A (shared by the pair): trans tile -> fp16 fragments (hi only) ----
    {
        const float4* gsrc = (const float4*)(tr + (size_t)b * TRANS_B_STRIDE
                                                + (size_t)h * ROW_FLOATS
                                                + (size_t)t * TRANS_T_STRIDE);
        #pragma unroll
        for (int i = 0; i < 7; i++) {
            int idx = i * 64 + lane64;         // 0..447 float4s
            int row = idx >> 4;                // 0..27
            int c4  = idx & 15;
            float4 v = __ldg(gsrc + idx);

            int mt  = row >> 4;
            int rp  = row & 15;
            int gg  = rp & 7;
            int rb  = rp >> 3;                 // 0 -> a0/a2, 1 -> a1/a3
            int kt  = c4 >> 2;
            int cpp = (c4 & 3) * 4;            // within-tile col base {0,4,8,12}
            int areg = rb + ((cpp >= 8) ? 2 : 0);
            int L0   = gg * 4 + ((cpp & 7) >> 1);

            uint32_t h0 = pack_f16x2(v.x, v.y);
            uint32_t h1 = pack_f16x2(v.z, v.w);

            uint32_t off0 = mt * 2048 + kt * 512 + (((L0)     ^ (kt << 1)) << 4) + areg * 4;
            uint32_t off1 = mt * 2048 + kt * 512 + (((L0 + 1) ^ (kt << 1)) << 4) + areg * 4;
            *(uint32_t*)(tslot + off0) = h0;
            *(uint32_t*)(tslot + off1) = h1;
        }
    }
    // quad barrier (4 warps = 2 pairs): A tiles staged before fragments are read
    asm volatile("bar.sync %0, 128;" :: "r"(barid) : "memory");

    // ---- GEMM: D(28x32slice) = A(28x64 fp16) x (Bhi + Blo)(64x32slice) ----
    float acc[2][4][4];
    #pragma unroll
    for (int mt = 0; mt < 2; mt++)
        #pragma unroll
        for (int nt = 0; nt < 4; nt++)
            #pragma unroll
            for (int j = 0; j < 4; j++) acc[mt][nt][j] = 0.0f;

    // uint2-granular fragment pointer for this (s,t,khalf,lane)
    const uint2* gwl = (const uint2*)(g_wfrag + (size_t)(s * T_CO + t) * (8 * 512))
                       + (size_t)khalf * 4 * 32 + lane;

    #pragma unroll 1
    for (int kt = 0; kt < 4; kt++) {
        // A fragment for this k-tile (reused for Bhi and Blo terms)
        const char* abase = tslot + kt * 512 + ((lane ^ (kt << 1)) << 4);
        uint4 A0 = *(const uint4*)(abase);
        uint4 A1 = *(const uint4*)(abase + 2048);

        // 8 independent B-fragment loads (Bhi tile kt, Blo tile kt+4)
        uint2 bh0 = gwl[((kt    ) * 8 + 0) * 32];
        uint2 bh1 = gwl[((kt    ) * 8 + 1) * 32];
        uint2 bh2 = gwl[((kt    ) * 8 + 2) * 32];
        uint2 bh3 = gwl[((kt    ) * 8 + 3) * 32];
        uint2 bl0 = gwl[((kt + 4) * 8 + 0) * 32];
        uint2 bl1 = gwl[((kt + 4) * 8 + 1) * 32];
        uint2 bl2 = gwl[((kt + 4) * 8 + 2) * 32];
        uint2 bl3 = gwl[((kt + 4) * 8 + 3) * 32];

        MMA16816(acc[0][0], A0, bh0.x, bh0.y);
        MMA16816(acc[1][0], A1, bh0.x, bh0.y);
        MMA16816(acc[0][1], A0, bh1.x, bh1.y);
        MMA16816(acc[1][1], A1, bh1.x, bh1.y);
        MMA16816(acc[0][2], A0, bh2.x, bh2.y);
        MMA16816(acc[1][2], A1, bh2.x, bh2.y);
        MMA16816(acc[0][3], A0, bh3.x, bh3.y);
        MMA16816(acc[1][3], A1, bh3.x, bh3.y);

        MMA16816(acc[0][0], A0, bl0.x, bl0.y);
        MMA16816(acc[1][0], A1, bl0.x, bl0.y);
        MMA16816(acc[0][1], A0, bl1.x, bl1.y);
        MMA16816(acc[1][1], A1, bl1.x, bl1.y);
        MMA16816(acc[0][2], A0, bl2.x, bl2.y);
        MMA16816(acc[1][2], A1, bl2.x, bl2.y);
        MMA16816(acc[0][3], A0, bl3.x, bl3.y);
        MMA16816(acc[1][3], A1, bl3.x, bl3.y);
    }

    // quad barrier: all 4 warps done reading A before D overwrites the slots
    asm volatile("bar.sync %0, 128;" :: "r"(barid) : "memory");

    // ---- write D into mix slot (reuses the pair's A region) ----
    #pragma unroll
    for (int mt = 0; mt < 2; mt++) {
        #pragma unroll
        for (int nt = 0; nt < 4; nt++) {
            int row0 = mt * 16 + g;
            int kp   = (khalf * 4 + nt) * 4 + tg;
            *(float2*)(tslot + row0 * MIX_ROW + kp * 8) =
                make_float2(acc[mt][nt][0], acc[mt][nt][1]);
            int row1 = row0 + 8;
            if (row1 < 28)
                *(float2*)(tslot + row1 * MIX_ROW + kp * 8) =
                    make_float2(acc[mt][nt][2], acc[mt][nt][3]);
        }
    }
    __syncthreads();

    // ---- combine: inverse 2D 4-pt WHT over t = 4u+v, scale 1/16, + bias ----
    if (tid < 896) {                       // w(28) x kpair(32)
        const int wrow = tid >> 5;
        const int kp   = tid & 31;

        float2 m[16];
        #pragma unroll
        for (int tt = 0; tt < 16; tt++)
            m[tt] = *(const float2*)(smc + tt * SLOT + wrow * MIX_ROW + kp * 8);

        #pragma unroll
        for (int u = 0; u < 4; u++) {
            float2 m0 = m[4*u], m1 = m[4*u+1], m2 = m[4*u+2], m3 = m[4*u+3];
            float2 s0 = f2add(m0, m1), d0 = f2sub(m0, m1);
            float2 s1 = f2add(m2, m3), d1 = f2sub(m2, m3);
            m[4*u + 0] = f2add(s0, s1);
            m[4*u + 1] = f2add(d0, d1);
            m[4*u + 2] = f2sub(s0, s1);
            m[4*u + 3] = f2sub(d0, d1);
        }

        const float2 bv = ((const float2*)bs)[kp];
        float* op = outp + (size_t)b * (112 * 112 * 64)
                         + (size_t)h * (4 * 112 * 64)
                         + (size_t)wrow * (4 * 64)
                         + 2 * kp;

        #pragma unroll
        for (int j = 0; j < 4; j++) {
            float2 r0 = m[j], r1 = m[4 + j], r2 = m[8 + j], r3 = m[12 + j];
            float2 s0 = f2add(r0, r1), d0 = f2sub(r0, r1);
            float2 s1 = f2add(r2, r3), d1 = f2sub(r2, r3);
            float2 o0 = f2add(s0, s1);
            float2 o1 = f2add(d0, d1);
            float2 o2 = f2sub(s0, s1);
            float2 o3 = f2sub(d0, d1);
            float2 v0 = make_float2(fmaf(o0.x, 0.0625f, bv.x), fmaf(o0.y, 0.0625f, bv.y));
            float2 v1 = make_float2(fmaf(o1.x, 0.0625f, bv.x), fmaf(o1.y, 0.0625f, bv.y));
            float2 v2 = make_float2(fmaf(o2.x, 0.0625f, bv.x), fmaf(o2.y, 0.0625f, bv.y));
            float2 v3 = make_float2(fmaf(o3.x, 0.0625f, bv.x), fmaf(o3.y, 0.0625f, bv.y));
            *reinterpret_cast<float2*>(op + 0 * 7168 + j * 64) = v0;
            *reinterpret_cast<float2*>(op + 1 * 7168 + j * 64) = v1;
            *reinterpret_cast<float2*>(op + 2 * 7168 + j * 64) = v2;
            *reinterpret_cast<float2*>(op + 3 * 7168 + j * 64) = v3;
        }
    }
}

extern "C" void kernel_launch(void* const* d_in, const int* in_sizes, int n_in,
                              void* d_out, int out_size) {
    (void)in_sizes; (void)n_in;
    const float* tr1 = (const float*)d_in[0];
    const float* tr2 = (const float*)d_in[1];
    const float* w1  = (const float*)d_in[2];
    const float* w2  = (const float*)d_in[3];
    const float* b1  = (const float*)d_in[4];
    const float* b2  = (const float*)d_in[5];
    float* out = (float*)d_out;

    prep_weights<<<512, 256>>>(w1, w2);

    cudaFuncSetAttribute(iwht2_mma_kernel,
                         cudaFuncAttributeMaxDynamicSharedMemorySize, SMEM_BYTES);
    size_t stream_stride = (size_t)out_size / 2;   // out1 then out2
    iwht2_mma_kernel<<<2 * BATCH * NH, NTHREADS, SMEM_BYTES>>>(
        tr1, tr2, b1, b2, out, stream_stride);
}

// round 11
// speedup vs baseline: 1.7238x; 1.0221x over previous
#include <cuda_runtime.h>
#include <cuda_fp16.h>
#include <cstdint>

// ---------------- problem constants ----------------
#define T_CO 16
#define BATCH 16
#define NH 28
#define NW 28
#define CCH 64
#define KCH 64
#define ROW_FLOATS (NW * CCH)                  // 1792
#define TRANS_T_STRIDE (BATCH * NH * NW * CCH) // 802816
#define TRANS_B_STRIDE (NH * NW * CCH)         // 50176

#define NTHREADS 512

// per-t smem slot (bytes): A frags (fp16, <=4092B) during GEMM,
// then reused as mix[t] khalf-slice (28 rows x 144B = 4032B)
#define SLOT 4096
#define SMEM_BYTES (T_CO * SLOT)               // 65536 -> 2 CTAs/SM
#define MIX_ROW 144                            // bytes per mix row (16 kpairs + pad)

// ---------------- weight fragments (prepacked fp16) ----------------
// layout [s][t][phys 8][nt 8][lane 32][2] b32 ; phys 0-3 = Bhi ktiles, 4-7 = Blo
__device__ uint32_t g_wfrag[2 * T_CO * 8 * 8 * 64];   // 512 KB

__device__ __forceinline__ uint32_t pack_f16x2(float lo_elem, float hi_elem) {
    uint32_t r;
    asm("cvt.rn.f16x2.f32 %0, %1, %2;" : "=r"(r) : "f"(hi_elem), "f"(lo_elem));
    return r;
}

__global__ void prep_weights(const float* __restrict__ w1, const float* __restrict__ w2) {
    int idx = blockIdx.x * 256 + threadIdx.x;      // 131072 total
    int r    = idx & 1;
    int lane = (idx >> 1) & 31;
    int nt   = (idx >> 6) & 7;
    int phys = (idx >> 9) & 7;
    int t    = (idx >> 12) & 15;
    int s    = idx >> 16;
    const float* w = s ? w2 : w1;
    int kchan = nt * 8 + (lane >> 2);
    int c     = (phys & 3) * 16 + (lane & 3) * 2 + r * 8;
    float v0 = w[(t * 64 + c) * 64 + kchan];
    float v1 = w[(t * 64 + c + 1) * 64 + kchan];
    if (phys >= 4) {   // lo residual tiles
        v0 = v0 - __half2float(__float2half_rn(v0));
        v1 = v1 - __half2float(__float2half_rn(v1));
    }
    g_wfrag[idx] = pack_f16x2(v0, v1);
}

// ---------------- main kernel ----------------
__device__ __forceinline__ float2 f2add(float2 a, float2 b) { return make_float2(a.x + b.x, a.y + b.y); }
__device__ __forceinline__ float2 f2sub(float2 a, float2 b) { return make_float2(a.x - b.x, a.y - b.y); }

#define MMA16816(d, a, b0, b1)                                               \
    asm("mma.sync.aligned.m16n8k16.row.col.f32.f16.f16.f32 "                 \
        "{%0,%1,%2,%3},{%4,%5,%6,%7},{%8,%9},{%0,%1,%2,%3};"                 \
        : "+f"((d)[0]), "+f"((d)[1]), "+f"((d)[2]), "+f"((d)[3])             \
        : "r"((a).x), "r"((a).y), "r"((a).z), "r"((a).w), "r"(b0), "r"(b1))

__global__ void __launch_bounds__(NTHREADS, 2)
iwht2_mma_kernel(const float* __restrict__ tr1, const float* __restrict__ tr2,
                 const float* __restrict__ b1,  const float* __restrict__ b2,
                 float* __restrict__ out, size_t out_stream_stride)
{
    extern __shared__ char smc[];

    // CTA = (s, b, h, khalf); khalf fastest -> sibling shares trans via L2
    const int bi    = blockIdx.x;
    const int khalf = bi & 1;
    const int h     = (bi >> 1) % NH;
    const int b     = ((bi >> 1) / NH) % BATCH;
    const int s     = bi / (2 * NH * BATCH);

    const float* tr = s ? tr2 : tr1;
    const float* bs = s ? b2  : b1;
    float* outp = out + (size_t)s * out_stream_stride;

    const int tid  = threadIdx.x;
    const int t    = tid >> 5;            // warp -> coefficient
    const int lane = tid & 31;
    const int g    = lane >> 2;           // group id (rows)
    const int tg   = lane & 3;            // thread-in-group (cols)
    char* tslot = smc + t * SLOT;

    // ---- stage A (warp-private): trans tile -> fp16 fragments ----
    {
        const float4* gsrc = (const float4*)(tr + (size_t)b * TRANS_B_STRIDE
                                                + (size_t)h * ROW_FLOATS
                                                + (size_t)t * TRANS_T_STRIDE);
        #pragma unroll
        for (int i = 0; i < 14; i++) {
            int idx = i * 32 + lane;           // 0..447 float4s
            int row = idx >> 4;                // 0..27
            int c4  = idx & 15;
            float4 v = __ldg(gsrc + idx);

            int mt  = row >> 4;
            int rp  = row & 15;
            int gg  = rp & 7;
            int rb  = rp >> 3;                 // 0 -> a0/a2, 1 -> a1/a3
            int kt  = c4 >> 2;
            int cpp = (c4 & 3) * 4;            // within-tile col base {0,4,8,12}
            int areg = rb + ((cpp >= 8) ? 2 : 0);
            int L0   = gg * 4 + ((cpp & 7) >> 1);

            uint32_t h0 = pack_f16x2(v.x, v.y);
            uint32_t h1 = pack_f16x2(v.z, v.w);

            uint32_t off0 = mt * 2048 + kt * 512 + (((L0)     ^ (kt << 1)) << 4) + areg * 4;
            uint32_t off1 = mt * 2048 + kt * 512 + (((L0 + 1) ^ (kt << 1)) << 4) + areg * 4;
            *(uint32_t*)(tslot + off0) = h0;
            *(uint32_t*)(tslot + off1) = h1;
        }
    }
    __syncwarp();

    // ---- GEMM: D(28x32slice) = A(28x64 fp16) x (Bhi + Blo)(64x32slice) ----
    float acc[2][4][4];
    #pragma unroll
    for (int mt = 0; mt < 2; mt++)
        #pragma unroll
        for (int nt = 0; nt < 4; nt++)
            #pragma unroll
            for (int j = 0; j < 4; j++) acc[mt][nt][j] = 0.0f;

    // uint2-granular fragment pointer for this (s,t,khalf,lane)
    const uint2* gwl = (const uint2*)(g_wfrag + (size_t)(s * T_CO + t) * (8 * 512))
                       + (size_t)khalf * 4 * 32 + lane;

    #pragma unroll 1
    for (int kt = 0; kt < 4; kt++) {
        const char* abase = tslot + kt * 512 + ((lane ^ (kt << 1)) << 4);
        uint4 A0 = *(const uint4*)(abase);
        uint4 A1 = *(const uint4*)(abase + 2048);

        // 8 independent B-fragment loads (Bhi tile kt, Blo tile kt+4)
        uint2 bh0 = gwl[((kt    ) * 8 + 0) * 32];
        uint2 bh1 = gwl[((kt    ) * 8 + 1) * 32];
        uint2 bh2 = gwl[((kt    ) * 8 + 2) * 32];
        uint2 bh3 = gwl[((kt    ) * 8 + 3) * 32];
        uint2 bl0 = gwl[((kt + 4) * 8 + 0) * 32];
        uint2 bl1 = gwl[((kt + 4) * 8 + 1) * 32];
        uint2 bl2 = gwl[((kt + 4) * 8 + 2) * 32];
        uint2 bl3 = gwl[((kt + 4) * 8 + 3) * 32];

        MMA16816(acc[0][0], A0, bh0.x, bh0.y);
        MMA16816(acc[1][0], A1, bh0.x, bh0.y);
        MMA16816(acc[0][1], A0, bh1.x, bh1.y);
        MMA16816(acc[1][1], A1, bh1.x, bh1.y);
        MMA16816(acc[0][2], A0, bh2.x, bh2.y);
        MMA16816(acc[1][2], A1, bh2.x, bh2.y);
        MMA16816(acc[0][3], A0, bh3.x, bh3.y);
        MMA16816(acc[1][3], A1, bh3.x, bh3.y);

        MMA16816(acc[0][0], A0, bl0.x, bl0.y);
        MMA16816(acc[1][0], A1, bl0.x, bl0.y);
        MMA16816(acc[0][1], A0, bl1.x, bl1.y);
        MMA16816(acc[1][1], A1, bl1.x, bl1.y);
        MMA16816(acc[0][2], A0, bl2.x, bl2.y);
        MMA16816(acc[1][2], A1, bl2.x, bl2.y);
        MMA16816(acc[0][3], A0, bl3.x, bl3.y);
        MMA16816(acc[1][3], A1, bl3.x, bl3.y);
    }

    // all lanes of this warp finished reading A before D overwrites the slot
    __syncwarp();

    // ---- write D into mix slot (warp-private reuse of the A region) ----
    #pragma unroll
    for (int mt = 0; mt < 2; mt++) {
        #pragma unroll
        for (int nt = 0; nt < 4; nt++) {
            int row0 = mt * 16 + g;
            int kp   = nt * 4 + tg;               // 0..15 within the khalf slice
            *(float2*)(tslot + row0 * MIX_ROW + kp * 8) =
                make_float2(acc[mt][nt][0], acc[mt][nt][1]);
            int row1 = row0 + 8;
            if (row1 < 28)
                *(float2*)(tslot + row1 * MIX_ROW + kp * 8) =
                    make_float2(acc[mt][nt][2], acc[mt][nt][3]);
        }
    }
    __syncthreads();

    // ---- combine: inverse 2D 4-pt WHT over t = 4u+v, scale 1/16, + bias ----
    if (tid < 448) {                       // w(28) x kpair(16)
        const int wrow = tid >> 4;
        const int kp   = tid & 15;

        float2 m[16];
        #pragma unroll
        for (int tt = 0; tt < 16; tt++)
            m[tt] = *(const float2*)(smc + tt * SLOT + wrow * MIX_ROW + kp * 8);

        #pragma unroll
        for (int u = 0; u < 4; u++) {
            float2 m0 = m[4*u], m1 = m[4*u+1], m2 = m[4*u+2], m3 = m[4*u+3];
            float2 s0 = f2add(m0, m1), d0 = f2sub(m0, m1);
            float2 s1 = f2add(m2, m3), d1 = f2sub(m2, m3);
            m[4*u + 0] = f2add(s0, s1);
            m[4*u + 1] = f2add(d0, d1);
            m[4*u + 2] = f2sub(s0, s1);
            m[4*u + 3] = f2sub(d0, d1);
        }

        const float2 bv = ((const float2*)bs)[khalf * 16 + kp];
        float* op = outp + (size_t)b * (112 * 112 * 64)
                         + (size_t)h * (4 * 112 * 64)
                         + (size_t)wrow * (4 * 64)
                         + khalf * 32 + 2 * kp;

        #pragma unroll
        for (int j = 0; j < 4; j++) {
            float2 r0 = m[j], r1 = m[4 + j], r2 = m[8 + j], r3 = m[12 + j];
            float2 s0 = f2add(r0, r1), d0 = f2sub(r0, r1);
            float2 s1 = f2add(r2, r3), d1 = f2sub(r2, r3);
            float2 o0 = f2add(s0, s1);
            float2 o1 = f2add(d0, d1);
            float2 o2 = f2sub(s0, s1);
            float2 o3 = f2sub(d0, d1);
            float2 v0 = make_float2(fmaf(o0.x, 0.0625f, bv.x), fmaf(o0.y, 0.0625f, bv.y));
            float2 v1 = make_float2(fmaf(o1.x, 0.0625f, bv.x), fmaf(o1.y, 0.0625f, bv.y));
            float2 v2 = make_float2(fmaf(o2.x, 0.0625f, bv.x), fmaf(o2.y, 0.0625f, bv.y));
            float2 v3 = make_float2(fmaf(o3.x, 0.0625f, bv.x), fmaf(o3.y, 0.0625f, bv.y));
            *reinterpret_cast<float2*>(op + 0 * 7168 + j * 64) = v0;
            *reinterpret_cast<float2*>(op + 1 * 7168 + j * 64) = v1;
            *reinterpret_cast<float2*>(op + 2 * 7168 + j * 64) = v2;
            *reinterpret_cast<float2*>(op + 3 * 7168 + j * 64) = v3;
        }
    }
}

extern "C" void kernel_launch(void* const* d_in, const int* in_sizes, int n_in,
                              void* d_out, int out_size) {
    (void)in_sizes; (void)n_in;
    const float* tr1 = (const float*)d_in[0];
    const float* tr2 = (const float*)d_in[1];
    const float* w1  = (const float*)d_in[2];
    const float* w2  = (const float*)d_in[3];
    const float* b1  = (const float*)d_in[4];
    const float* b2  = (const float*)d_in[5];
    float* out = (float*)d_out;

    prep_weights<<<512, 256>>>(w1, w2);

    cudaFuncSetAttribute(iwht2_mma_kernel,
                         cudaFuncAttributeMaxDynamicSharedMemorySize, SMEM_BYTES);
    size_t stream_stride = (size_t)out_size / 2;   // out1 then out2
    iwht2_mma_kernel<<<2 * BATCH * NH * 2, NTHREADS, SMEM_BYTES>>>(
        tr1, tr2, b1, b2, out, stream_stride);
}

// round 12
// speedup vs baseline: 1.8761x; 1.0884x over previous
#include <cuda_runtime.h>
#include <cuda_fp16.h>
#include <cstdint>

// ---------------- problem constants ----------------
#define T_CO 16
#define BATCH 16
#define NH 28
#define NW 28
#define CCH 64
#define KCH 64
#define ROW_FLOATS (NW * CCH)                  // 1792
#define TRANS_T_STRIDE (BATCH * NH * NW * CCH) // 802816
#define TRANS_B_STRIDE (NH * NW * CCH)         // 50176

#define NTHREADS 512

// per-t smem slot (bytes): A tile fp16, linear layout, 144B-padded rows
// (32 row slots so tile-1 fragment reads stay in-bounds), reused as mix slice.
#define AROW 144
#define SLOT 4608
#define SMEM_BYTES (T_CO * SLOT)               // 73728 -> 2 CTAs/SM
#define MIX_ROW 144

// ---------------- weight fragments (prepacked fp16, uint4 granularity) ------
// layout [s][t][phys 8][ntp 4][lane 32] x uint4
//   phys 0-3 = Bhi k-tiles, 4-7 = Blo k-tiles
//   uint4 = { nt=2*ntp   : (b0,b1),  nt=2*ntp+1 : (b0,b1) }
__device__ uint32_t g_wfrag[2 * T_CO * 8 * 4 * 32 * 4];   // 512 KB

__device__ __forceinline__ uint32_t pack_f16x2(float lo_elem, float hi_elem) {
    uint32_t r;
    asm("cvt.rn.f16x2.f32 %0, %1, %2;" : "=r"(r) : "f"(hi_elem), "f"(lo_elem));
    return r;
}

__global__ void prep_weights(const float* __restrict__ w1, const float* __restrict__ w2) {
    int idx = blockIdx.x * 256 + threadIdx.x;      // 65536 threads, 1 uint2 each
    int half = idx & 1;
    int lane = (idx >> 1) & 31;
    int ntp  = (idx >> 6) & 3;
    int phys = (idx >> 8) & 7;
    int t    = (idx >> 11) & 15;
    int s    = idx >> 15;
    const float* w = s ? w2 : w1;
    int nt    = ntp * 2 + half;
    int kchan = nt * 8 + (lane >> 2);
    int c     = (phys & 3) * 16 + (lane & 3) * 2;
    float v00 = w[(t * 64 + c    ) * 64 + kchan];
    float v01 = w[(t * 64 + c + 1) * 64 + kchan];
    float v10 = w[(t * 64 + c + 8) * 64 + kchan];
    float v11 = w[(t * 64 + c + 9) * 64 + kchan];
    if (phys >= 4) {   // lo residual tiles
        v00 = v00 - __half2float(__float2half_rn(v00));
        v01 = v01 - __half2float(__float2half_rn(v01));
        v10 = v10 - __half2float(__float2half_rn(v10));
        v11 = v11 - __half2float(__float2half_rn(v11));
    }
    uint2 o;
    o.x = pack_f16x2(v00, v01);
    o.y = pack_f16x2(v10, v11);
    size_t u2idx = ((((size_t)((s * 16 + t) * 8 + phys) * 4 + ntp) * 32 + lane) << 1) + half;
    ((uint2*)g_wfrag)[u2idx] = o;
}

// ---------------- main kernel ----------------
__device__ __forceinline__ float2 f2add(float2 a, float2 b) { return make_float2(a.x + b.x, a.y + b.y); }
__device__ __forceinline__ float2 f2sub(float2 a, float2 b) { return make_float2(a.x - b.x, a.y - b.y); }

#define MMA4(d, a0, a1, a2, a3, b0, b1)                                      \
    asm("mma.sync.aligned.m16n8k16.row.col.f32.f16.f16.f32 "                 \
        "{%0,%1,%2,%3},{%4,%5,%6,%7},{%8,%9},{%0,%1,%2,%3};"                 \
        : "+f"((d)[0]), "+f"((d)[1]), "+f"((d)[2]), "+f"((d)[3])             \
        : "r"(a0), "r"(a1), "r"(a2), "r"(a3), "r"(b0), "r"(b1))

__global__ void __launch_bounds__(NTHREADS, 2)
iwht2_mma_kernel(const float* __restrict__ tr1, const float* __restrict__ tr2,
                 const float* __restrict__ b1,  const float* __restrict__ b2,
                 float* __restrict__ out, size_t out_stream_stride)
{
    extern __shared__ char smc[];

    // CTA = (s, b, h, khalf); khalf fastest -> sibling shares trans via L2
    const int bi    = blockIdx.x;
    const int khalf = bi & 1;
    const int h     = (bi >> 1) % NH;
    const int b     = ((bi >> 1) / NH) % BATCH;
    const int s     = bi / (2 * NH * BATCH);

    const float* tr = s ? tr2 : tr1;
    const float* bs = s ? b2  : b1;
    float* outp = out + (size_t)s * out_stream_stride;

    const int tid  = threadIdx.x;
    const int t    = tid >> 5;            // warp -> coefficient
    const int lane = tid & 31;
    const int g    = lane >> 2;           // group id (rows)
    const int tg   = lane & 3;            // thread-in-group (cols)
    char* tslot = smc + t * SLOT;

    // ---- stage A (warp-private): trans tile -> fp16, linear 144B rows ----
    {
        const float4* gsrc = (const float4*)(tr + (size_t)b * TRANS_B_STRIDE
                                                + (size_t)h * ROW_FLOATS
                                                + (size_t)t * TRANS_T_STRIDE);
        #pragma unroll
        for (int i = 0; i < 14; i++) {
            int idx = i * 32 + lane;           // 0..447 float4s
            int row = idx >> 4;                // 0..27
            int c4  = idx & 15;
            float4 v = __ldg(gsrc + idx);
            uint2 hh;
            hh.x = pack_f16x2(v.x, v.y);       // cols 4c4, 4c4+1
            hh.y = pack_f16x2(v.z, v.w);       // cols 4c4+2, 4c4+3
            *(uint2*)(tslot + row * AROW + c4 * 8) = hh;
        }
    }
    __syncwarp();

    // ---- GEMM: D(28x32slice) = A(28x64 fp16) x (Bhi + Blo)(64x32slice) ----
    float acc[2][4][4];
    #pragma unroll
    for (int mt = 0; mt < 2; mt++)
        #pragma unroll
        for (int nt = 0; nt < 4; nt++)
            #pragma unroll
            for (int j = 0; j < 4; j++) acc[mt][nt][j] = 0.0f;

    // A fragment base for this lane (PTX m16n8k16: a0=[g][2tg], a1=[g+8], a2=+8cols)
    const char* aw = tslot + g * AROW + tg * 4;
    // B fragment base: [phys][ntp][lane] uint4; this warp uses ntp = khalf*2, +1
    const char* gw = (const char*)g_wfrag
                   + (size_t)(s * T_CO + t) * 16384
                   + (size_t)(khalf * 2 * 32 + lane) * 16;

    #pragma unroll 1
    for (int kt = 0; kt < 4; kt++) {
        // B: 4 coalesced LDG.128 (hi ntp0, hi ntp1, lo ntp0, lo ntp1)
        uint4 bh0 = *(const uint4*)(gw + kt * 2048);
        uint4 bh1 = *(const uint4*)(gw + kt * 2048 + 512);
        uint4 bl0 = *(const uint4*)(gw + kt * 2048 + 8192);
        uint4 bl1 = *(const uint4*)(gw + kt * 2048 + 8704);

        // A: 8 conflict-free LDS.32 (two m16 tiles)
        const char* a = aw + kt * 32;
        uint32_t a00 = *(const uint32_t*)(a);
        uint32_t a01 = *(const uint32_t*)(a + 8 * AROW);
        uint32_t a02 = *(const uint32_t*)(a + 16);
        uint32_t a03 = *(const uint32_t*)(a + 8 * AROW + 16);
        uint32_t a10 = *(const uint32_t*)(a + 16 * AROW);
        uint32_t a11 = *(const uint32_t*)(a + 24 * AROW);
        uint32_t a12 = *(const uint32_t*)(a + 16 * AROW + 16);
        uint32_t a13 = *(const uint32_t*)(a + 24 * AROW + 16);

        MMA4(acc[0][0], a00, a01, a02, a03, bh0.x, bh0.y);
        MMA4(acc[1][0], a10, a11, a12, a13, bh0.x, bh0.y);
        MMA4(acc[0][1], a00, a01, a02, a03, bh0.z, bh0.w);
        MMA4(acc[1][1], a10, a11, a12, a13, bh0.z, bh0.w);
        MMA4(acc[0][2], a00, a01, a02, a03, bh1.x, bh1.y);
        MMA4(acc[1][2], a10, a11, a12, a13, bh1.x, bh1.y);
        MMA4(acc[0][3], a00, a01, a02, a03, bh1.z, bh1.w);
        MMA4(acc[1][3], a10, a11, a12, a13, bh1.z, bh1.w);

        MMA4(acc[0][0], a00, a01, a02, a03, bl0.x, bl0.y);
        MMA4(acc[1][0], a10, a11, a12, a13, bl0.x, bl0.y);
        MMA4(acc[0][1], a00, a01, a02, a03, bl0.z, bl0.w);
        MMA4(acc[1][1], a10, a11, a12, a13, bl0.z, bl0.w);
        MMA4(acc[0][2], a00, a01, a02, a03, bl1.x, bl1.y);
        MMA4(acc[1][2], a10, a11, a12, a13, bl1.x, bl1.y);
        MMA4(acc[0][3], a00, a01, a02, a03, bl1.z, bl1.w);
        MMA4(acc[1][3], a10, a11, a12, a13, bl1.z, bl1.w);
    }

    __syncwarp();

    // ---- write D into mix slot (warp-private reuse of the A region) ----
    #pragma unroll
    for (int mt = 0; mt < 2; mt++) {
        #pragma unroll
        for (int nt = 0; nt < 4; nt++) {
            int row0 = mt * 16 + g;
            int kp   = nt * 4 + tg;               // 0..15 within the khalf slice
            *(float2*)(tslot + row0 * MIX_ROW + kp * 8) =
                make_float2(acc[mt][nt][0], acc[mt][nt][1]);
            int row1 = row0 + 8;
            if (row1 < 28)
                *(float2*)(tslot + row1 * MIX_ROW + kp * 8) =
                    make_float2(acc[mt][nt][2], acc[mt][nt][3]);
        }
    }
    __syncthreads();

    // ---- combine: inverse 2D 4-pt WHT over t = 4u+v, scale 1/16, + bias ----
    if (tid < 448) {                       // w(28) x kpair(16)
        const int wrow = tid >> 4;
        const int kp   = tid & 15;

        float2 m[16];
        #pragma unroll
        for (int tt = 0; tt < 16; tt++)
            m[tt] = *(const float2*)(smc + tt * SLOT + wrow * MIX_ROW + kp * 8);

        #pragma unroll
        for (int u = 0; u < 4; u++) {
            float2 m0 = m[4*u], m1 = m[4*u+1], m2 = m[4*u+2], m3 = m[4*u+3];
            float2 s0 = f2add(m0, m1), d0 = f2sub(m0, m1);
            float2 s1 = f2add(m2, m3), d1 = f2sub(m2, m3);
            m[4*u + 0] = f2add(s0, s1);
            m[4*u + 1] = f2add(d0, d1);
            m[4*u + 2] = f2sub(s0, s1);
            m[4*u + 3] = f2sub(d0, d1);
        }

        const float2 bv = ((const float2*)bs)[khalf * 16 + kp];
        float* op = outp + (size_t)b * (112 * 112 * 64)
                         + (size_t)h * (4 * 112 * 64)
                         + (size_t)wrow * (4 * 64)
                         + khalf * 32 + 2 * kp;

        #pragma unroll
        for (int j = 0; j < 4; j++) {
            float2 r0 = m[j], r1 = m[4 + j], r2 = m[8 + j], r3 = m[12 + j];
            float2 s0 = f2add(r0, r1), d0 = f2sub(r0, r1);
            float2 s1 = f2add(r2, r3), d1 = f2sub(r2, r3);
            float2 o0 = f2add(s0, s1);
            float2 o1 = f2add(d0, d1);
            float2 o2 = f2sub(s0, s1);
            float2 o3 = f2sub(d0, d1);
            float2 v0 = make_float2(fmaf(o0.x, 0.0625f, bv.x), fmaf(o0.y, 0.0625f, bv.y));
            float2 v1 = make_float2(fmaf(o1.x, 0.0625f, bv.x), fmaf(o1.y, 0.0625f, bv.y));
            float2 v2 = make_float2(fmaf(o2.x, 0.0625f, bv.x), fmaf(o2.y, 0.0625f, bv.y));
            float2 v3 = make_float2(fmaf(o3.x, 0.0625f, bv.x), fmaf(o3.y, 0.0625f, bv.y));
            *reinterpret_cast<float2*>(op + 0 * 7168 + j * 64) = v0;
            *reinterpret_cast<float2*>(op + 1 * 7168 + j * 64) = v1;
            *reinterpret_cast<float2*>(op + 2 * 7168 + j * 64) = v2;
            *reinterpret_cast<float2*>(op + 3 * 7168 + j * 64) = v3;
        }
    }
}

extern "C" void kernel_launch(void* const* d_in, const int* in_sizes, int n_in,
                              void* d_out, int out_size) {
    (void)in_sizes; (void)n_in;
    const float* tr1 = (const float*)d_in[0];
    const float* tr2 = (const float*)d_in[1];
    const float* w1  = (const float*)d_in[2];
    const float* w2  = (const float*)d_in[3];
    const float* b1  = (const float*)d_in[4];
    const float* b2  = (const float*)d_in[5];
    float* out = (float*)d_out;

    prep_weights<<<256, 256>>>(w1, w2);

    cudaFuncSetAttribute(iwht2_mma_kernel,
                         cudaFuncAttributeMaxDynamicSharedMemorySize, SMEM_BYTES);
    size_t stream_stride = (size_t)out_size / 2;   // out1 then out2
    iwht2_mma_kernel<<<2 * BATCH * NH * 2, NTHREADS, SMEM_BYTES>>>(
        tr1, tr2, b1, b2, out, stream_stride);
}

// round 13
// speedup vs baseline: 2.0148x; 1.0739x over previous
#include <cuda_runtime.h>
#include <cuda_fp16.h>
#include <cstdint>

// ---------------- problem constants ----------------
#define T_CO 16
#define BATCH 16
#define NH 28
#define NW 28
#define CCH 64
#define KCH 64
#define ROW_FLOATS (NW * CCH)                  // 1792
#define TRANS_T_STRIDE (BATCH * NH * NW * CCH) // 802816
#define TRANS_B_STRIDE (NH * NW * CCH)         // 50176

#define NTHREADS 512

// per-t smem slot (bytes): A tile fp16, linear layout, 144B-padded rows
// (32 row slots so tile-1 fragment reads stay in-bounds), reused as mix slice.
#define AROW 144
#define SLOT 4608
#define SMEM_BYTES (T_CO * SLOT)               // 73728 -> 2 CTAs/SM
#define MIX_ROW 144

// ---------------- weight fragments (prepacked fp16, single-rounded) ---------
// layout [s][t][kt 4][ntp 4][lane 32] x uint4
//   uint4 = { nt=2*ntp : (b0,b1),  nt=2*ntp+1 : (b0,b1) }
__device__ uint32_t g_wfrag[2 * T_CO * 4 * 4 * 32 * 4];   // 256 KB

__device__ __forceinline__ uint32_t pack_f16x2(float lo_elem, float hi_elem) {
    uint32_t r;
    asm("cvt.rn.f16x2.f32 %0, %1, %2;" : "=r"(r) : "f"(hi_elem), "f"(lo_elem));
    return r;
}

__global__ void prep_weights(const float* __restrict__ w1, const float* __restrict__ w2) {
    int idx = blockIdx.x * 256 + threadIdx.x;      // 32768 threads, 1 uint2 each
    int half = idx & 1;
    int lane = (idx >> 1) & 31;
    int ntp  = (idx >> 6) & 3;
    int kt   = (idx >> 8) & 3;
    int t    = (idx >> 10) & 15;
    int s    = idx >> 14;
    const float* w = s ? w2 : w1;
    int nt    = ntp * 2 + half;
    int kchan = nt * 8 + (lane >> 2);
    int c     = kt * 16 + (lane & 3) * 2;
    float v00 = w[(t * 64 + c    ) * 64 + kchan];
    float v01 = w[(t * 64 + c + 1) * 64 + kchan];
    float v10 = w[(t * 64 + c + 8) * 64 + kchan];
    float v11 = w[(t * 64 + c + 9) * 64 + kchan];
    uint2 o;
    o.x = pack_f16x2(v00, v01);
    o.y = pack_f16x2(v10, v11);
    size_t u2idx = ((((size_t)((s * 16 + t) * 4 + kt) * 4 + ntp) * 32 + lane) << 1) + half;
    ((uint2*)g_wfrag)[u2idx] = o;
}

// ---------------- main kernel ----------------
__device__ __forceinline__ float2 f2add(float2 a, float2 b) { return make_float2(a.x + b.x, a.y + b.y); }
__device__ __forceinline__ float2 f2sub(float2 a, float2 b) { return make_float2(a.x - b.x, a.y - b.y); }

#define MMA4(d, a0, a1, a2, a3, b0, b1)                                      \
    asm("mma.sync.aligned.m16n8k16.row.col.f32.f16.f16.f32 "                 \
        "{%0,%1,%2,%3},{%4,%5,%6,%7},{%8,%9},{%0,%1,%2,%3};"                 \
        : "+f"((d)[0]), "+f"((d)[1]), "+f"((d)[2]), "+f"((d)[3])             \
        : "r"(a0), "r"(a1), "r"(a2), "r"(a3), "r"(b0), "r"(b1))

__global__ void __launch_bounds__(NTHREADS, 2)
iwht2_mma_kernel(const float* __restrict__ tr1, const float* __restrict__ tr2,
                 const float* __restrict__ b1,  const float* __restrict__ b2,
                 float* __restrict__ out, size_t out_stream_stride)
{
    extern __shared__ char smc[];

    // CTA = (s, b, h, khalf); khalf fastest -> sibling shares trans via L2
    const int bi    = blockIdx.x;
    const int khalf = bi & 1;
    const int h     = (bi >> 1) % NH;
    const int b     = ((bi >> 1) / NH) % BATCH;
    const int s     = bi / (2 * NH * BATCH);

    const float* tr = s ? tr2 : tr1;
    const float* bs = s ? b2  : b1;
    float* outp = out + (size_t)s * out_stream_stride;

    const int tid  = threadIdx.x;
    const int t    = tid >> 5;            // warp -> coefficient
    const int lane = tid & 31;
    const int g    = lane >> 2;           // group id (rows)
    const int tg   = lane & 3;            // thread-in-group (cols)
    char* tslot = smc + t * SLOT;

    // ---- stage A (warp-private): trans tile -> fp16, linear 144B rows ----
    {
        const float4* gsrc = (const float4*)(tr + (size_t)b * TRANS_B_STRIDE
                                                + (size_t)h * ROW_FLOATS
                                                + (size_t)t * TRANS_T_STRIDE);
        #pragma unroll
        for (int i = 0; i < 14; i++) {
            int idx = i * 32 + lane;           // 0..447 float4s
            int row = idx >> 4;                // 0..27
            int c4  = idx & 15;
            float4 v = __ldg(gsrc + idx);
            uint2 hh;
            hh.x = pack_f16x2(v.x, v.y);       // cols 4c4, 4c4+1
            hh.y = pack_f16x2(v.z, v.w);       // cols 4c4+2, 4c4+3
            *(uint2*)(tslot + row * AROW + c4 * 8) = hh;
        }
    }
    __syncwarp();

    // ---- GEMM: D(28x32slice) = A(28x64 fp16) x B(64x32slice fp16) ----
    float acc[2][4][4];
    #pragma unroll
    for (int mt = 0; mt < 2; mt++)
        #pragma unroll
        for (int nt = 0; nt < 4; nt++)
            #pragma unroll
            for (int j = 0; j < 4; j++) acc[mt][nt][j] = 0.0f;

    // A fragment base for this lane (PTX m16n8k16: a0=[g][2tg], a1=[g+8], a2=+8cols)
    const char* aw = tslot + g * AROW + tg * 4;
    // B fragment base: [kt][ntp][lane] uint4; this warp uses ntp = khalf*2, +1
    const char* gw = (const char*)g_wfrag
                   + (size_t)(s * T_CO + t) * 8192
                   + (size_t)(khalf * 2 * 32 + lane) * 16;

    #pragma unroll 1
    for (int kt = 0; kt < 4; kt++) {
        // B: 2 coalesced LDG.128 (ntp0, ntp1)
        uint4 bh0 = *(const uint4*)(gw + kt * 2048);
        uint4 bh1 = *(const uint4*)(gw + kt * 2048 + 512);

        // A: 8 conflict-free LDS.32 (two m16 tiles)
        const char* a = aw + kt * 32;
        uint32_t a00 = *(const uint32_t*)(a);
        uint32_t a01 = *(const uint32_t*)(a + 8 * AROW);
        uint32_t a02 = *(const uint32_t*)(a + 16);
        uint32_t a03 = *(const uint32_t*)(a + 8 * AROW + 16);
        uint32_t a10 = *(const uint32_t*)(a + 16 * AROW);
        uint32_t a11 = *(const uint32_t*)(a + 24 * AROW);
        uint32_t a12 = *(const uint32_t*)(a + 16 * AROW + 16);
        uint32_t a13 = *(const uint32_t*)(a + 24 * AROW + 16);

        MMA4(acc[0][0], a00, a01, a02, a03, bh0.x, bh0.y);
        MMA4(acc[1][0], a10, a11, a12, a13, bh0.x, bh0.y);
        MMA4(acc[0][1], a00, a01, a02, a03, bh0.z, bh0.w);
        MMA4(acc[1][1], a10, a11, a12, a13, bh0.z, bh0.w);
        MMA4(acc[0][2], a00, a01, a02, a03, bh1.x, bh1.y);
        MMA4(acc[1][2], a10, a11, a12, a13, bh1.x, bh1.y);
        MMA4(acc[0][3], a00, a01, a02, a03, bh1.z, bh1.w);
        MMA4(acc[1][3], a10, a11, a12, a13, bh1.z, bh1.w);
    }

    __syncwarp();

    // ---- write D into mix slot (warp-private reuse of the A region) ----
    #pragma unroll
    for (int mt = 0; mt < 2; mt++) {
        #pragma unroll
        for (int nt = 0; nt < 4; nt++) {
            int row0 = mt * 16 + g;
            int kp   = nt * 4 + tg;               // 0..15 within the khalf slice
            *(float2*)(tslot + row0 * MIX_ROW + kp * 8) =
                make_float2(acc[mt][nt][0], acc[mt][nt][1]);
            int row1 = row0 + 8;
            if (row1 < 28)
                *(float2*)(tslot + row1 * MIX_ROW + kp * 8) =
                    make_float2(acc[mt][nt][2], acc[mt][nt][3]);
        }
    }
    __syncthreads();

    // ---- combine: inverse 2D 4-pt WHT over t = 4u+v, scale 1/16, + bias ----
    if (tid < 448) {                       // w(28) x kpair(16)
        const int wrow = tid >> 4;
        const int kp   = tid & 15;

        float2 m[16];
        #pragma unroll
        for (int tt = 0; tt < 16; tt++)
            m[tt] = *(const float2*)(smc + tt * SLOT + wrow * MIX_ROW + kp * 8);

        #pragma unroll
        for (int u = 0; u < 4; u++) {
            float2 m0 = m[4*u], m1 = m[4*u+1], m2 = m[4*u+2], m3 = m[4*u+3];
            float2 s0 = f2add(m0, m1), d0 = f2sub(m0, m1);
            float2 s1 = f2add(m2, m3), d1 = f2sub(m2, m3);
            m[4*u + 0] = f2add(s0, s1);
            m[4*u + 1] = f2add(d0, d1);
            m[4*u + 2] = f2sub(s0, s1);
            m[4*u + 3] = f2sub(d0, d1);
        }

        const float2 bv = ((const float2*)bs)[khalf * 16 + kp];
        float* op = outp + (size_t)b * (112 * 112 * 64)
                         + (size_t)h * (4 * 112 * 64)
                         + (size_t)wrow * (4 * 64)
                         + khalf * 32 + 2 * kp;

        #pragma unroll
        for (int j = 0; j < 4; j++) {
            float2 r0 = m[j], r1 = m[4 + j], r2 = m[8 + j], r3 = m[12 + j];
            float2 s0 = f2add(r0, r1), d0 = f2sub(r0, r1);
            float2 s1 = f2add(r2, r3), d1 = f2sub(r2, r3);
            float2 o0 = f2add(s0, s1);
            float2 o1 = f2add(d0, d1);
            float2 o2 = f2sub(s0, s1);
            float2 o3 = f2sub(d0, d1);
            float2 v0 = make_float2(fmaf(o0.x, 0.0625f, bv.x), fmaf(o0.y, 0.0625f, bv.y));
            float2 v1 = make_float2(fmaf(o1.x, 0.0625f, bv.x), fmaf(o1.y, 0.0625f, bv.y));
            float2 v2 = make_float2(fmaf(o2.x, 0.0625f, bv.x), fmaf(o2.y, 0.0625f, bv.y));
            float2 v3 = make_float2(fmaf(o3.x, 0.0625f, bv.x), fmaf(o3.y, 0.0625f, bv.y));
            *reinterpret_cast<float2*>(op + 0 * 7168 + j * 64) = v0;
            *reinterpret_cast<float2*>(op + 1 * 7168 + j * 64) = v1;
            *reinterpret_cast<float2*>(op + 2 * 7168 + j * 64) = v2;
            *reinterpret_cast<float2*>(op + 3 * 7168 + j * 64) = v3;
        }
    }
}

extern "C" void kernel_launch(void* const* d_in, const int* in_sizes, int n_in,
                              void* d_out, int out_size) {
    (void)in_sizes; (void)n_in;
    const float* tr1 = (const float*)d_in[0];
    const float* tr2 = (const float*)d_in[1];
    const float* w1  = (const float*)d_in[2];
    const float* w2  = (const float*)d_in[3];
    const float* b1  = (const float*)d_in[4];
    const float* b2  = (const float*)d_in[5];
    float* out = (float*)d_out;

    prep_weights<<<128, 256>>>(w1, w2);

    cudaFuncSetAttribute(iwht2_mma_kernel,
                         cudaFuncAttributeMaxDynamicSharedMemorySize, SMEM_BYTES);
    size_t stream_stride = (size_t)out_size / 2;   // out1 then out2
    iwht2_mma_kernel<<<2 * BATCH * NH * 2, NTHREADS, SMEM_BYTES>>>(
        tr1, tr2, b1, b2, out, stream_stride);
}

// round 14
// speedup vs baseline: 2.0248x; 1.0050x over previous
#include <cuda_runtime.h>
#include <cuda_fp16.h>
#include <cstdint>

// ---------------- problem constants ----------------
#define T_CO 16
#define BATCH 16
#define NH 28
#define NW 28
#define CCH 64
#define KCH 64
#define ROW_FLOATS (NW * CCH)                  // 1792
#define TRANS_T_STRIDE (BATCH * NH * NW * CCH) // 802816
#define TRANS_B_STRIDE (NH * NW * CCH)         // 50176

#define NTHREADS 512

// per-t smem slot (bytes): A tile fp16, linear layout, 144B-padded rows
// (32 row slots so tile-1 fragment reads stay in-bounds), reused as mix slice.
#define AROW 144
#define SLOT 4608
#define SMEM_BYTES (T_CO * SLOT)               // 73728 -> 2 CTAs/SM
#define MIX_ROW 144

// ---------------- weight fragments (prepacked fp16, single-rounded) ---------
// layout [s][t][kt 4][ntp 4][lane 32] x uint4
//   uint4 = { nt=2*ntp : (b0,b1),  nt=2*ntp+1 : (b0,b1) }
__device__ uint32_t g_wfrag[2 * T_CO * 4 * 4 * 32 * 4];   // 256 KB

__device__ __forceinline__ uint32_t pack_f16x2(float lo_elem, float hi_elem) {
    uint32_t r;
    asm("cvt.rn.f16x2.f32 %0, %1, %2;" : "=r"(r) : "f"(hi_elem), "f"(lo_elem));
    return r;
}

__global__ void prep_weights(const float* __restrict__ w1, const float* __restrict__ w2) {
    int idx = blockIdx.x * 256 + threadIdx.x;      // 32768 threads, 1 uint2 each
    int half = idx & 1;
    int lane = (idx >> 1) & 31;
    int ntp  = (idx >> 6) & 3;
    int kt   = (idx >> 8) & 3;
    int t    = (idx >> 10) & 15;
    int s    = idx >> 14;
    const float* w = s ? w2 : w1;
    int nt    = ntp * 2 + half;
    int kchan = nt * 8 + (lane >> 2);
    int c     = kt * 16 + (lane & 3) * 2;
    float v00 = w[(t * 64 + c    ) * 64 + kchan];
    float v01 = w[(t * 64 + c + 1) * 64 + kchan];
    float v10 = w[(t * 64 + c + 8) * 64 + kchan];
    float v11 = w[(t * 64 + c + 9) * 64 + kchan];
    uint2 o;
    o.x = pack_f16x2(v00, v01);
    o.y = pack_f16x2(v10, v11);
    size_t u2idx = ((((size_t)((s * 16 + t) * 4 + kt) * 4 + ntp) * 32 + lane) << 1) + half;
    ((uint2*)g_wfrag)[u2idx] = o;
}

// ---------------- main kernel ----------------
__device__ __forceinline__ float2 f2add(float2 a, float2 b) { return make_float2(a.x + b.x, a.y + b.y); }
__device__ __forceinline__ float2 f2sub(float2 a, float2 b) { return make_float2(a.x - b.x, a.y - b.y); }

__device__ __forceinline__ uint32_t smem_u32(const void* p) {
    uint32_t a;
    asm("{ .reg .u64 t; cvta.to.shared.u64 t, %1; cvt.u32.u64 %0, t; }" : "=r"(a) : "l"(p));
    return a;
}

__device__ __forceinline__ void ldmatrix_x4(uint32_t& r0, uint32_t& r1,
                                            uint32_t& r2, uint32_t& r3,
                                            uint32_t saddr) {
    asm volatile("ldmatrix.sync.aligned.m8n8.x4.shared.b16 {%0,%1,%2,%3}, [%4];"
                 : "=r"(r0), "=r"(r1), "=r"(r2), "=r"(r3) : "r"(saddr));
}

#define MMA4(d, a0, a1, a2, a3, b0, b1)                                      \
    asm("mma.sync.aligned.m16n8k16.row.col.f32.f16.f16.f32 "                 \
        "{%0,%1,%2,%3},{%4,%5,%6,%7},{%8,%9},{%0,%1,%2,%3};"                 \
        : "+f"((d)[0]), "+f"((d)[1]), "+f"((d)[2]), "+f"((d)[3])             \
        : "r"(a0), "r"(a1), "r"(a2), "r"(a3), "r"(b0), "r"(b1))

__global__ void __launch_bounds__(NTHREADS, 2)
iwht2_mma_kernel(const float* __restrict__ tr1, const float* __restrict__ tr2,
                 const float* __restrict__ b1,  const float* __restrict__ b2,
                 float* __restrict__ out, size_t out_stream_stride)
{
    extern __shared__ char smc[];

    // CTA = (s, b, h, khalf); khalf fastest -> sibling shares trans via L2
    const int bi    = blockIdx.x;
    const int khalf = bi & 1;
    const int h     = (bi >> 1) % NH;
    const int b     = ((bi >> 1) / NH) % BATCH;
    const int s     = bi / (2 * NH * BATCH);

    const float* tr = s ? tr2 : tr1;
    const float* bs = s ? b2  : b1;
    float* outp = out + (size_t)s * out_stream_stride;

    const int tid  = threadIdx.x;
    const int t    = tid >> 5;            // warp -> coefficient
    const int lane = tid & 31;
    const int g    = lane >> 2;           // group id (rows)
    const int tg   = lane & 3;            // thread-in-group (cols)
    char* tslot = smc + t * SLOT;

    // B fragment base: [kt][ntp][lane] uint4; this warp uses ntp = khalf*2, +1
    const char* gw = (const char*)g_wfrag
                   + (size_t)(s * T_CO + t) * 8192
                   + (size_t)(khalf * 2 * 32 + lane) * 16;

    // prefetch kt=0 B fragments; staging below hides the latency
    uint4 bc0 = *(const uint4*)(gw);
    uint4 bc1 = *(const uint4*)(gw + 512);

    // ---- stage A (warp-private): trans tile -> fp16, linear 144B rows ----
    {
        const float4* gsrc = (const float4*)(tr + (size_t)b * TRANS_B_STRIDE
                                                + (size_t)h * ROW_FLOATS
                                                + (size_t)t * TRANS_T_STRIDE);
        #pragma unroll
        for (int i = 0; i < 14; i++) {
            int idx = i * 32 + lane;           // 0..447 float4s
            int row = idx >> 4;                // 0..27
            int c4  = idx & 15;
            float4 v = __ldg(gsrc + idx);
            uint2 hh;
            hh.x = pack_f16x2(v.x, v.y);       // cols 4c4, 4c4+1
            hh.y = pack_f16x2(v.z, v.w);       // cols 4c4+2, 4c4+3
            *(uint2*)(tslot + row * AROW + c4 * 8) = hh;
        }
    }
    __syncwarp();

    // ---- GEMM: D(28x32slice) = A(28x64 fp16) x B(64x32slice fp16) ----
    float acc[2][4][4];
    #pragma unroll
    for (int mt = 0; mt < 2; mt++)
        #pragma unroll
        for (int nt = 0; nt < 4; nt++)
            #pragma unroll
            for (int j = 0; j < 4; j++) acc[mt][nt][j] = 0.0f;

    // ldmatrix.x4 lane->row-address: mtx = lane>>3; rows (mtx&1)*8 + (lane&7),
    // k-col halves selected by (mtx>>1)*16
    const uint32_t abase0 = smem_u32(tslot)
                          + ((lane & 7) + ((lane >> 3) & 1) * 8) * AROW
                          + ((lane >> 4)) * 16;
    const uint32_t abase1 = abase0 + 16 * AROW;

    #pragma unroll 1
    for (int kt = 0; kt < 4; kt++) {
        // prefetch next iteration's B (covered by this iteration's MMAs)
        uint4 bn0, bn1;
        if (kt < 3) {
            bn0 = *(const uint4*)(gw + (kt + 1) * 2048);
            bn1 = *(const uint4*)(gw + (kt + 1) * 2048 + 512);
        }

        uint32_t a00, a01, a02, a03, a10, a11, a12, a13;
        ldmatrix_x4(a00, a01, a02, a03, abase0 + kt * 32);
        ldmatrix_x4(a10, a11, a12, a13, abase1 + kt * 32);

        MMA4(acc[0][0], a00, a01, a02, a03, bc0.x, bc0.y);
        MMA4(acc[1][0], a10, a11, a12, a13, bc0.x, bc0.y);
        MMA4(acc[0][1], a00, a01, a02, a03, bc0.z, bc0.w);
        MMA4(acc[1][1], a10, a11, a12, a13, bc0.z, bc0.w);
        MMA4(acc[0][2], a00, a01, a02, a03, bc1.x, bc1.y);
        MMA4(acc[1][2], a10, a11, a12, a13, bc1.x, bc1.y);
        MMA4(acc[0][3], a00, a01, a02, a03, bc1.z, bc1.w);
        MMA4(acc[1][3], a10, a11, a12, a13, bc1.z, bc1.w);

        bc0 = bn0;
        bc1 = bn1;
    }

    __syncwarp();

    // ---- write D into mix slot (warp-private reuse of the A region) ----
    #pragma unroll
    for (int mt = 0; mt < 2; mt++) {
        #pragma unroll
        for (int nt = 0; nt < 4; nt++) {
            int row0 = mt * 16 + g;
            int kp   = nt * 4 + tg;               // 0..15 within the khalf slice
            *(float2*)(tslot + row0 * MIX_ROW + kp * 8) =
                make_float2(acc[mt][nt][0], acc[mt][nt][1]);
            int row1 = row0 + 8;
            if (row1 < 28)
                *(float2*)(tslot + row1 * MIX_ROW + kp * 8) =
                    make_float2(acc[mt][nt][2], acc[mt][nt][3]);
        }
    }
    __syncthreads();

    // ---- combine: inverse 2D 4-pt WHT over t = 4u+v, scale 1/16, + bias ----
    if (tid < 448) {                       // w(28) x kpair(16)
        const int wrow = tid >> 4;
        const int kp   = tid & 15;

        float2 m[16];
        #pragma unroll
        for (int tt = 0; tt < 16; tt++)
            m[tt] = *(const float2*)(smc + tt * SLOT + wrow * MIX_ROW + kp * 8);

        #pragma unroll
        for (int u = 0; u < 4; u++) {
            float2 m0 = m[4*u], m1 = m[4*u+1], m2 = m[4*u+2], m3 = m[4*u+3];
            float2 s0 = f2add(m0, m1), d0 = f2sub(m0, m1);
            float2 s1 = f2add(m2, m3), d1 = f2sub(m2, m3);
            m[4*u + 0] = f2add(s0, s1);
            m[4*u + 1] = f2add(d0, d1);
            m[4*u + 2] = f2sub(s0, s1);
            m[4*u + 3] = f2sub(d0, d1);
        }

        const float2 bv = ((const float2*)bs)[khalf * 16 + kp];
        float* op = outp + (size_t)b * (112 * 112 * 64)
                         + (size_t)h * (4 * 112 * 64)
                         + (size_t)wrow * (4 * 64)
                         + khalf * 32 + 2 * kp;

        #pragma unroll
        for (int j = 0; j < 4; j++) {
            float2 r0 = m[j], r1 = m[4 + j], r2 = m[8 + j], r3 = m[12 + j];
            float2 s0 = f2add(r0, r1), d0 = f2sub(r0, r1);
            float2 s1 = f2add(r2, r3), d1 = f2sub(r2, r3);
            float2 o0 = f2add(s0, s1);
            float2 o1 = f2add(d0, d1);
            float2 o2 = f2sub(s0, s1);
            float2 o3 = f2sub(d0, d1);
            float2 v0 = make_float2(fmaf(o0.x, 0.0625f, bv.x), fmaf(o0.y, 0.0625f, bv.y));
            float2 v1 = make_float2(fmaf(o1.x, 0.0625f, bv.x), fmaf(o1.y, 0.0625f, bv.y));
            float2 v2 = make_float2(fmaf(o2.x, 0.0625f, bv.x), fmaf(o2.y, 0.0625f, bv.y));
            float2 v3 = make_float2(fmaf(o3.x, 0.0625f, bv.x), fmaf(o3.y, 0.0625f, bv.y));
            *reinterpret_cast<float2*>(op + 0 * 7168 + j * 64) = v0;
            *reinterpret_cast<float2*>(op + 1 * 7168 + j * 64) = v1;
            *reinterpret_cast<float2*>(op + 2 * 7168 + j * 64) = v2;
            *reinterpret_cast<float2*>(op + 3 * 7168 + j * 64) = v3;
        }
    }
}

extern "C" void kernel_launch(void* const* d_in, const int* in_sizes, int n_in,
                              void* d_out, int out_size) {
    (void)in_sizes; (void)n_in;
    const float* tr1 = (const float*)d_in[0];
    const float* tr2 = (const float*)d_in[1];
    const float* w1  = (const float*)d_in[2];
    const float* w2  = (const float*)d_in[3];
    const float* b1  = (const float*)d_in[4];
    const float* b2  = (const float*)d_in[5];
    float* out = (float*)d_out;

    prep_weights<<<128, 256>>>(w1, w2);

    cudaFuncSetAttribute(iwht2_mma_kernel,
                         cudaFuncAttributeMaxDynamicSharedMemorySize, SMEM_BYTES);
    size_t stream_stride = (size_t)out_size / 2;   // out1 then out2
    iwht2_mma_kernel<<<2 * BATCH * NH * 2, NTHREADS, SMEM_BYTES>>>(
        tr1, tr2, b1, b2, out, stream_stride);
}